// round 3
// baseline (speedup 1.0000x reference)
#include <cuda_runtime.h>
#include <math.h>

#define S    512
#define DIM  2048
#define H    32
#define HK   4
#define HD   128
#define NQK  (H*HD)    // 4096
#define NKV  (HK*HD)   // 512
#define NE   64
#define TOPK 8
#define FF   768
#define EPS  1e-6f

// ---------------- scratch (static device globals; no allocation) -------------
__device__ float g_xn[S*DIM];
__device__ float g_q [S*NQK];
__device__ float g_k [S*NKV];
__device__ float g_v [S*NKV];
__device__ float g_attn[S*NQK];
__device__ float g_hn[S*DIM];
__device__ float g_mid[(size_t)NE*S*FF];     // ~100 MB, worst-case per-expert rows
__device__ int   g_ecnt[NE];
__device__ int   g_etok[NE*S];
__device__ float g_ew  [NE*S];

// ---------------- small utility kernels --------------------------------------
__global__ void zero_counts_kernel() {
    if (threadIdx.x < NE) g_ecnt[threadIdx.x] = 0;
}

__global__ void rmsnorm_kernel(const float* __restrict__ x,
                               const float* __restrict__ w,
                               float* __restrict__ out) {
    int row = blockIdx.x;
    const float* xr = x + (size_t)row * DIM;
    float ss = 0.f;
    for (int i = threadIdx.x; i < DIM; i += 256) { float v = xr[i]; ss += v * v; }
    __shared__ float red[256];
    red[threadIdx.x] = ss; __syncthreads();
    for (int st = 128; st > 0; st >>= 1) {
        if (threadIdx.x < st) red[threadIdx.x] += red[threadIdx.x + st];
        __syncthreads();
    }
    float rstd = rsqrtf(red[0] / (float)DIM + EPS);
    for (int i = threadIdx.x; i < DIM; i += 256)
        out[(size_t)row * DIM + i] = xr[i] * rstd * w[i];
}

// ---------------- generic NT GEMM: C[M,N] = A[M,K] @ B[N,K]^T (+resid) -------
// BM=BN=64, BK=16, 256 threads, 4x4 microtile. M,N % 64 == 0, K % 16 == 0.
__global__ __launch_bounds__(256) void gemm_nt_kernel(
    const float* __restrict__ A, const float* __restrict__ B,
    float* __restrict__ C, int M, int N, int K,
    const float* __restrict__ resid)
{
    __shared__ float As[16][64];
    __shared__ float Bs[16][64];
    int mBase = blockIdx.y * 64, nBase = blockIdx.x * 64;
    int tid = threadIdx.x;
    int tx = tid & 15, ty = tid >> 4;
    float acc[4][4] = {};
    for (int kt = 0; kt < K; kt += 16) {
        int idx = tid * 4; int r = idx >> 4; int c = idx & 15;
        float4 va = *(const float4*)(A + (size_t)(mBase + r) * K + kt + c);
        As[c][r] = va.x; As[c+1][r] = va.y; As[c+2][r] = va.z; As[c+3][r] = va.w;
        float4 vb = *(const float4*)(B + (size_t)(nBase + r) * K + kt + c);
        Bs[c][r] = vb.x; Bs[c+1][r] = vb.y; Bs[c+2][r] = vb.z; Bs[c+3][r] = vb.w;
        __syncthreads();
        #pragma unroll
        for (int kk = 0; kk < 16; kk++) {
            float4 a4 = *(const float4*)&As[kk][ty * 4];
            float4 b4 = *(const float4*)&Bs[kk][tx * 4];
            float a[4] = {a4.x, a4.y, a4.z, a4.w};
            float b[4] = {b4.x, b4.y, b4.z, b4.w};
            #pragma unroll
            for (int i = 0; i < 4; i++)
                #pragma unroll
                for (int j = 0; j < 4; j++) acc[i][j] += a[i] * b[j];
        }
        __syncthreads();
    }
    #pragma unroll
    for (int i = 0; i < 4; i++) {
        int m = mBase + ty * 4 + i;
        #pragma unroll
        for (int j = 0; j < 4; j++) {
            int n = nBase + tx * 4 + j;
            float v = acc[i][j];
            if (resid) v += resid[(size_t)m * N + n];
            C[(size_t)m * N + n] = v;
        }
    }
}

// ---------------- per-head RMSNorm + RoPE (in place on q/k) ------------------
__global__ void qknorm_rope_kernel(const float* __restrict__ qnw,
                                   const float* __restrict__ knw,
                                   const float* __restrict__ cosp,
                                   const float* __restrict__ sinp)
{
    int s = blockIdx.x, h2 = blockIdx.y, d = threadIdx.x;   // 128 threads
    float* ptr; const float* w;
    if (h2 < H) { ptr = g_q + (size_t)s * NQK + h2 * HD;      w = qnw; }
    else        { ptr = g_k + (size_t)s * NKV + (h2 - H) * HD; w = knw; }
    __shared__ float row[HD];
    __shared__ float red[HD];
    float v = ptr[d];
    red[d] = v * v; __syncthreads();
    for (int st = 64; st > 0; st >>= 1) {
        if (d < st) red[d] += red[d + st];
        __syncthreads();
    }
    float rstd = rsqrtf(red[0] / (float)HD + EPS);
    row[d] = v * rstd * w[d];
    __syncthreads();
    float rot = (d < 64) ? -row[d + 64] : row[d - 64];
    ptr[d] = row[d] * cosp[s * HD + d] + rot * sinp[s * HD + d];
}

// ---------------- causal attention: one block per (query, head) --------------
__global__ void attn_kernel()
{
    int s = blockIdx.x, h = blockIdx.y, tid = threadIdx.x;  // 128 threads
    int kvh = h / (H / HK);
    __shared__ float qs[HD];
    __shared__ float p[S];
    __shared__ float red[128];
    qs[tid] = g_q[(size_t)s * NQK + h * HD + tid];
    __syncthreads();
    int nk = s + 1;
    const float scale = rsqrtf((float)HD);
    float lmax = -1e30f;
    for (int key = tid; key < nk; key += 128) {
        const float* kr = g_k + (size_t)key * NKV + kvh * HD;
        float acc = 0.f;
        #pragma unroll 8
        for (int d2 = 0; d2 < HD; d2++) acc += qs[d2] * kr[d2];
        acc *= scale;
        p[key] = acc;
        lmax = fmaxf(lmax, acc);
    }
    red[tid] = lmax; __syncthreads();
    for (int st = 64; st > 0; st >>= 1) {
        if (tid < st) red[tid] = fmaxf(red[tid], red[tid + st]);
        __syncthreads();
    }
    float m = red[0];
    __syncthreads();
    float lsum = 0.f;
    for (int key = tid; key < nk; key += 128) {
        float e = expf(p[key] - m);
        p[key] = e; lsum += e;
    }
    red[tid] = lsum; __syncthreads();
    for (int st = 64; st > 0; st >>= 1) {
        if (tid < st) red[tid] += red[tid + st];
        __syncthreads();
    }
    float inv = 1.f / red[0];
    __syncthreads();
    float acc = 0.f;                                 // thread = output dim
    for (int key = 0; key < nk; key++)
        acc += p[key] * g_v[(size_t)key * NKV + kvh * HD + tid];
    g_attn[(size_t)s * NQK + h * HD + tid] = acc * inv;
}

// ---------------- router: softmax + top-8 + scatter into expert lists --------
__global__ void router_kernel(const float* __restrict__ rw)
{
    int t = blockIdx.x, tid = threadIdx.x;   // 128 threads
    __shared__ float hrow[DIM];
    __shared__ float logits[NE];
    for (int i = tid; i < DIM; i += 128) hrow[i] = g_hn[(size_t)t * DIM + i];
    __syncthreads();
    if (tid < NE) {
        const float* r = rw + (size_t)tid * DIM;
        float acc = 0.f;
        for (int i = 0; i < DIM; i++) acc += hrow[i] * r[i];
        logits[tid] = acc;
    }
    __syncthreads();
    if (tid == 0) {
        float m = -1e30f;
        for (int e = 0; e < NE; e++) m = fmaxf(m, logits[e]);
        float pr[NE]; float sum = 0.f;
        for (int e = 0; e < NE; e++) { pr[e] = expf(logits[e] - m); sum += pr[e]; }
        float invs = 1.f / sum;
        for (int e = 0; e < NE; e++) pr[e] *= invs;
        int   ti[TOPK]; float tw[TOPK]; float wsum = 0.f;
        for (int kk = 0; kk < TOPK; kk++) {
            int best = 0; float bv = -1.f;
            for (int e = 0; e < NE; e++) if (pr[e] > bv) { bv = pr[e]; best = e; }
            ti[kk] = best; tw[kk] = bv; pr[best] = -2.f; wsum += bv;
        }
        float inv = 1.f / (wsum + 1e-20f);
        for (int kk = 0; kk < TOPK; kk++) {
            int e = ti[kk];
            int pos = atomicAdd(&g_ecnt[e], 1);
            g_etok[e * S + pos] = t;
            g_ew  [e * S + pos] = tw[kk] * inv;
        }
    }
}

// ---------------- MoE phase 1: mid = silu(hn@gate^T) * (hn@up^T) -------------
// grid: (FF/64=12, S/64=8, NE), 256 threads, expert-grouped gathered GEMM.
__global__ __launch_bounds__(256) void moe_mid_kernel(
    const float* __restrict__ gate_w, const float* __restrict__ up_w)
{
    int e = blockIdx.z;
    int Me = g_ecnt[e];
    int rowBase = blockIdx.y * 64;
    if (rowBase >= Me) return;
    int ffBase = blockIdx.x * 64;
    __shared__ float As[16][64];
    __shared__ float Gs[16][64];
    __shared__ float Us[16][64];
    __shared__ int tok[64];
    int tid = threadIdx.x;
    if (tid < 64) tok[tid] = g_etok[e * S + min(rowBase + tid, Me - 1)];
    __syncthreads();
    const float* gw = gate_w + (size_t)e * FF * DIM;
    const float* uw = up_w   + (size_t)e * FF * DIM;
    int tx = tid & 15, ty = tid >> 4;
    float g[4][4] = {}, u[4][4] = {};
    for (int kt = 0; kt < DIM; kt += 16) {
        int idx = tid * 4; int r = idx >> 4; int c = idx & 15;
        float4 va = *(const float4*)(g_hn + (size_t)tok[r] * DIM + kt + c);
        As[c][r] = va.x; As[c+1][r] = va.y; As[c+2][r] = va.z; As[c+3][r] = va.w;
        float4 vg = *(const float4*)(gw + (size_t)(ffBase + r) * DIM + kt + c);
        Gs[c][r] = vg.x; Gs[c+1][r] = vg.y; Gs[c+2][r] = vg.z; Gs[c+3][r] = vg.w;
        float4 vu = *(const float4*)(uw + (size_t)(ffBase + r) * DIM + kt + c);
        Us[c][r] = vu.x; Us[c+1][r] = vu.y; Us[c+2][r] = vu.z; Us[c+3][r] = vu.w;
        __syncthreads();
        #pragma unroll
        for (int kk = 0; kk < 16; kk++) {
            float4 a4 = *(const float4*)&As[kk][ty * 4];
            float4 g4 = *(const float4*)&Gs[kk][tx * 4];
            float4 u4 = *(const float4*)&Us[kk][tx * 4];
            float a[4] = {a4.x, a4.y, a4.z, a4.w};
            float gb[4] = {g4.x, g4.y, g4.z, g4.w};
            float ub[4] = {u4.x, u4.y, u4.z, u4.w};
            #pragma unroll
            for (int i = 0; i < 4; i++)
                #pragma unroll
                for (int j = 0; j < 4; j++) {
                    g[i][j] += a[i] * gb[j];
                    u[i][j] += a[i] * ub[j];
                }
        }
        __syncthreads();
    }
    #pragma unroll
    for (int i = 0; i < 4; i++) {
        int slot = rowBase + ty * 4 + i;
        if (slot >= Me) continue;
        #pragma unroll
        for (int j = 0; j < 4; j++) {
            float gg = g[i][j];
            float mid = gg / (1.f + expf(-gg)) * u[i][j];   // silu(g)*u
            g_mid[(size_t)e * S * FF + (size_t)slot * FF + ffBase + tx * 4 + j] = mid;
        }
    }
}

// ---------------- MoE phase 2: out[token] += w * (mid @ down^T) --------------
// grid: (DIM/64=32, S/64=8, NE), 256 threads.
__global__ __launch_bounds__(256) void moe_down_kernel(
    const float* __restrict__ down_w, float* __restrict__ out)
{
    int e = blockIdx.z;
    int Me = g_ecnt[e];
    int rowBase = blockIdx.y * 64;
    if (rowBase >= Me) return;
    int nBase = blockIdx.x * 64;
    __shared__ float As[16][64];
    __shared__ float Bs[16][64];
    __shared__ int tok[64];
    __shared__ float wts[64];
    int tid = threadIdx.x;
    if (tid < 64) {
        int sl = min(rowBase + tid, Me - 1);
        tok[tid] = g_etok[e * S + sl];
        wts[tid] = g_ew  [e * S + sl];
    }
    __syncthreads();
    const float* dw = down_w + (size_t)e * DIM * FF;
    const float* mbase = g_mid + (size_t)e * S * FF;
    int tx = tid & 15, ty = tid >> 4;
    float acc[4][4] = {};
    for (int kt = 0; kt < FF; kt += 16) {
        int idx = tid * 4; int r = idx >> 4; int c = idx & 15;
        float4 va = *(const float4*)(mbase + (size_t)(rowBase + r) * FF + kt + c);
        As[c][r] = va.x; As[c+1][r] = va.y; As[c+2][r] = va.z; As[c+3][r] = va.w;
        float4 vb = *(const float4*)(dw + (size_t)(nBase + r) * FF + kt + c);
        Bs[c][r] = vb.x; Bs[c+1][r] = vb.y; Bs[c+2][r] = vb.z; Bs[c+3][r] = vb.w;
        __syncthreads();
        #pragma unroll
        for (int kk = 0; kk < 16; kk++) {
            float4 a4 = *(const float4*)&As[kk][ty * 4];
            float4 b4 = *(const float4*)&Bs[kk][tx * 4];
            float a[4] = {a4.x, a4.y, a4.z, a4.w};
            float b[4] = {b4.x, b4.y, b4.z, b4.w};
            #pragma unroll
            for (int i = 0; i < 4; i++)
                #pragma unroll
                for (int j = 0; j < 4; j++) acc[i][j] += a[i] * b[j];
        }
        __syncthreads();
    }
    #pragma unroll
    for (int i = 0; i < 4; i++) {
        int slot = rowBase + ty * 4 + i;
        if (slot >= Me) continue;
        int t = tok[ty * 4 + i];
        float w = wts[ty * 4 + i];
        #pragma unroll
        for (int j = 0; j < 4; j++)
            atomicAdd(&out[(size_t)t * DIM + nBase + tx * 4 + j], acc[i][j] * w);
    }
}

// ---------------- launch ------------------------------------------------------
extern "C" void kernel_launch(void* const* d_in, const int* in_sizes, int n_in,
                              void* d_out, int out_size)
{
    const float* x    = (const float*)d_in[0];
    const float* cosp = (const float*)d_in[1];
    const float* sinp = (const float*)d_in[2];
    const float* n1w  = (const float*)d_in[3];
    const float* wq   = (const float*)d_in[4];
    const float* wk   = (const float*)d_in[5];
    const float* wv   = (const float*)d_in[6];
    const float* wo   = (const float*)d_in[7];
    const float* qnw  = (const float*)d_in[8];
    const float* knw  = (const float*)d_in[9];
    const float* n2w  = (const float*)d_in[10];
    const float* rw   = (const float*)d_in[11];
    const float* gw   = (const float*)d_in[12];
    const float* uw   = (const float*)d_in[13];
    const float* dw   = (const float*)d_in[14];
    float* out = (float*)d_out;

    float *xn, *q, *k, *v, *attn, *hn;
    cudaGetSymbolAddress((void**)&xn,   g_xn);
    cudaGetSymbolAddress((void**)&q,    g_q);
    cudaGetSymbolAddress((void**)&k,    g_k);
    cudaGetSymbolAddress((void**)&v,    g_v);
    cudaGetSymbolAddress((void**)&attn, g_attn);
    cudaGetSymbolAddress((void**)&hn,   g_hn);

    zero_counts_kernel<<<1, 64>>>();
    rmsnorm_kernel<<<S, 256>>>(x, n1w, xn);
    gemm_nt_kernel<<<dim3(NQK/64, S/64), 256>>>(xn, wq, q, S, NQK, DIM, nullptr);
    gemm_nt_kernel<<<dim3(NKV/64, S/64), 256>>>(xn, wk, k, S, NKV, DIM, nullptr);
    gemm_nt_kernel<<<dim3(NKV/64, S/64), 256>>>(xn, wv, v, S, NKV, DIM, nullptr);
    qknorm_rope_kernel<<<dim3(S, H + HK), HD>>>(qnw, knw, cosp, sinp);
    attn_kernel<<<dim3(S, H), 128>>>();
    gemm_nt_kernel<<<dim3(DIM/64, S/64), 256>>>(attn, wo, out, S, DIM, NQK, x); // h -> d_out
    rmsnorm_kernel<<<S, 256>>>(out, n2w, hn);
    router_kernel<<<S, 128>>>(rw);
    moe_mid_kernel<<<dim3(FF/64, S/64, NE), 256>>>(gw, uw);
    moe_down_kernel<<<dim3(DIM/64, S/64, NE), 256>>>(dw, out);
}

// round 4
// speedup vs baseline: 1.3570x; 1.3570x over previous
#include <cuda_runtime.h>
#include <math.h>

#define S    512
#define DIM  2048
#define H    32
#define HK   4
#define HD   128
#define NQK  (H*HD)    // 4096
#define NKV  (HK*HD)   // 512
#define NE   64
#define TOPK 8
#define FF   768
#define EPS  1e-6f
#define GRP  (H/HK)    // 8

// ---------------- scratch (static device globals; no allocation) -------------
__device__ float g_xn[S*DIM];
__device__ float g_qt[(size_t)H*S*HD];      // [h][s][d]
__device__ float g_kt[(size_t)HK*S*HD];
__device__ float g_vt[(size_t)HK*S*HD];
__device__ float g_scores[(size_t)H*S*S];   // 33.5 MB
__device__ float g_attn[S*NQK];             // [s][h*HD+d]
__device__ float g_hn[S*DIM];
__device__ float g_midg[(size_t)NE*S*FF];   // gate raw -> silu(g)*u
__device__ float g_midu[(size_t)NE*S*FF];   // up raw
__device__ int   g_ecnt[NE];
__device__ int   g_etok[NE*S];
__device__ float g_ew  [NE*S];

// =============================================================================
// Core: 64x128 output tile, 256 threads, 4x8 microtile, BK=16, double-buffered.
// C[64,128] += A[64,K] * B^T  (BT=true: B is [N,K] row-major; BT=false: B is
// [K,N] row-major).  rowIdx (smem, 64 entries) gathers A rows if non-null.
// =============================================================================
template<bool BT>
__device__ __forceinline__ void sgemm_core(
    const float* __restrict__ Abase, int lda,
    const int* __restrict__ rowIdx, int mBase,
    const float* __restrict__ Bbase, int ldb, int nBase,
    int K, float (&acc)[4][8])
{
    __shared__ float As[2][16][68];
    __shared__ float Bs[2][16][132];
    const int tid = threadIdx.x;
    const int ar = tid >> 2, ac = (tid & 3) * 4;          // A: 64 rows x 16 k
    const float* Aptr = Abase + (size_t)(rowIdx ? rowIdx[ar] : (mBase + ar)) * lda + ac;
    int br, bc;
    const float* Bptr;
    if (BT) { br = tid >> 1;  bc = (tid & 1) * 8;         // B: 128 rows x 16 k
              Bptr = Bbase + (size_t)(nBase + br) * ldb + bc; }
    else    { br = tid >> 4;  bc = (tid & 15) * 8;        // B: 16 k x 128 n
              Bptr = Bbase + (size_t)br * ldb + nBase + bc; }

    const int ktiles = K >> 4;
    float4 a  = *(const float4*)Aptr;
    float4 b0 = *(const float4*)Bptr;
    float4 b1 = *(const float4*)(Bptr + 4);
    As[0][ac+0][ar]=a.x; As[0][ac+1][ar]=a.y; As[0][ac+2][ar]=a.z; As[0][ac+3][ar]=a.w;
    if (BT) {
        Bs[0][bc+0][br]=b0.x; Bs[0][bc+1][br]=b0.y; Bs[0][bc+2][br]=b0.z; Bs[0][bc+3][br]=b0.w;
        Bs[0][bc+4][br]=b1.x; Bs[0][bc+5][br]=b1.y; Bs[0][bc+6][br]=b1.z; Bs[0][bc+7][br]=b1.w;
    } else {
        *(float4*)&Bs[0][br][bc]   = b0;
        *(float4*)&Bs[0][br][bc+4] = b1;
    }
    __syncthreads();

    const int ty = tid >> 4, tx = tid & 15;
    for (int t = 0; t < ktiles; t++) {
        const int buf = t & 1;
        if (t + 1 < ktiles) {   // prefetch next tile into registers
            a = *(const float4*)(Aptr + (t+1)*16);
            const float* bp = BT ? (Bptr + (t+1)*16)
                                 : (Bptr + (size_t)(t+1)*16*ldb);
            b0 = *(const float4*)bp;
            b1 = *(const float4*)(bp + 4);
        }
        #pragma unroll
        for (int kk = 0; kk < 16; kk++) {
            float4 av  = *(const float4*)&As[buf][kk][ty*4];
            float4 bv0 = *(const float4*)&Bs[buf][kk][tx*8];
            float4 bv1 = *(const float4*)&Bs[buf][kk][tx*8+4];
            float aa[4] = {av.x, av.y, av.z, av.w};
            float bb[8] = {bv0.x,bv0.y,bv0.z,bv0.w, bv1.x,bv1.y,bv1.z,bv1.w};
            #pragma unroll
            for (int i = 0; i < 4; i++)
                #pragma unroll
                for (int j = 0; j < 8; j++)
                    acc[i][j] += aa[i] * bb[j];
        }
        if (t + 1 < ktiles) {
            const int nb = buf ^ 1;
            As[nb][ac+0][ar]=a.x; As[nb][ac+1][ar]=a.y; As[nb][ac+2][ar]=a.z; As[nb][ac+3][ar]=a.w;
            if (BT) {
                Bs[nb][bc+0][br]=b0.x; Bs[nb][bc+1][br]=b0.y; Bs[nb][bc+2][br]=b0.z; Bs[nb][bc+3][br]=b0.w;
                Bs[nb][bc+4][br]=b1.x; Bs[nb][bc+5][br]=b1.y; Bs[nb][bc+6][br]=b1.z; Bs[nb][bc+7][br]=b1.w;
            } else {
                *(float4*)&Bs[nb][br][bc]   = b0;
                *(float4*)&Bs[nb][br][bc+4] = b1;
            }
            __syncthreads();
        }
    }
}

// ---------------- small utility kernels --------------------------------------
__global__ void zero_counts_kernel() {
    if (threadIdx.x < NE) g_ecnt[threadIdx.x] = 0;
}

__global__ void rmsnorm_kernel(const float* __restrict__ x,
                               const float* __restrict__ w,
                               float* __restrict__ out) {
    int row = blockIdx.x;
    const float* xr = x + (size_t)row * DIM;
    float ss = 0.f;
    for (int i = threadIdx.x; i < DIM; i += 256) { float v = xr[i]; ss += v * v; }
    __shared__ float red[256];
    red[threadIdx.x] = ss; __syncthreads();
    for (int st = 128; st > 0; st >>= 1) {
        if (threadIdx.x < st) red[threadIdx.x] += red[threadIdx.x + st];
        __syncthreads();
    }
    float rstd = rsqrtf(red[0] / (float)DIM + EPS);
    for (int i = threadIdx.x; i < DIM; i += 256)
        out[(size_t)row * DIM + i] = xr[i] * rstd * w[i];
}

// ---------------- fused QKV GEMM, writes per-head-contiguous -----------------
// grid (40, 8): x = head-tile (0-31 q, 32-35 k, 36-39 v), y = m-tile
__global__ __launch_bounds__(256) void qkv_kernel(
    const float* __restrict__ xn, const float* __restrict__ wq,
    const float* __restrict__ wk, const float* __restrict__ wv)
{
    int nt = blockIdx.x, mBase = blockIdx.y * 64;
    const float* B; float* out; int head;
    if (nt < H)           { B = wq; head = nt;          out = g_qt + (size_t)head * S * HD; }
    else if (nt < H + HK) { B = wk; head = nt - H;      out = g_kt + (size_t)head * S * HD; }
    else                  { B = wv; head = nt - H - HK; out = g_vt + (size_t)head * S * HD; }
    float acc[4][8] = {};
    sgemm_core<true>(xn, DIM, nullptr, mBase, B, DIM, head * HD, DIM, acc);
    int ty = threadIdx.x >> 4, tx = threadIdx.x & 15;
    #pragma unroll
    for (int i = 0; i < 4; i++) {
        size_t m = mBase + ty * 4 + i;
        #pragma unroll
        for (int j = 0; j < 8; j++)
            out[m * HD + tx * 8 + j] = acc[i][j];
    }
}

// ---------------- per-head RMSNorm + RoPE on [h][s][d] layout ----------------
__global__ void qknorm_rope_kernel(const float* __restrict__ qnw,
                                   const float* __restrict__ knw,
                                   const float* __restrict__ cosp,
                                   const float* __restrict__ sinp)
{
    int s = blockIdx.x, h2 = blockIdx.y, d = threadIdx.x;   // 128 threads
    float* ptr; const float* w;
    if (h2 < H) { ptr = g_qt + (size_t)h2      * S * HD + (size_t)s * HD; w = qnw; }
    else        { ptr = g_kt + (size_t)(h2 - H)* S * HD + (size_t)s * HD; w = knw; }
    __shared__ float row[HD];
    __shared__ float red[HD];
    float v = ptr[d];
    red[d] = v * v; __syncthreads();
    for (int st = 64; st > 0; st >>= 1) {
        if (d < st) red[d] += red[d + st];
        __syncthreads();
    }
    float rstd = rsqrtf(red[0] / (float)HD + EPS);
    row[d] = v * rstd * w[d];
    __syncthreads();
    float rot = (d < 64) ? -row[d + 64] : row[d - 64];
    ptr[d] = row[d] * cosp[s * HD + d] + rot * sinp[s * HD + d];
}

// ---------------- scores = (Q K^T)/sqrt(HD), causal blocks skipped -----------
// grid (4, 8, 32): x = key-tile(128), y = query-tile(64), z = head
__global__ __launch_bounds__(256) void scores_kernel()
{
    int h = blockIdx.z, mBase = blockIdx.y * 64, nBase = blockIdx.x * 128;
    if (nBase > mBase + 63) return;               // fully above diagonal
    int kvh = h / GRP;
    float acc[4][8] = {};
    sgemm_core<true>(g_qt + (size_t)h   * S * HD, HD, nullptr, mBase,
                     g_kt + (size_t)kvh * S * HD, HD, nBase, HD, acc);
    const float alpha = 0.08838834764831845f;     // 1/sqrt(128)
    float* C = g_scores + (size_t)h * S * S;
    int ty = threadIdx.x >> 4, tx = threadIdx.x & 15;
    #pragma unroll
    for (int i = 0; i < 4; i++)
        #pragma unroll
        for (int j = 0; j < 8; j++)
            C[(size_t)(mBase + ty*4 + i) * S + nBase + tx*8 + j] = acc[i][j] * alpha;
}

// ---------------- causal row softmax (zero-fills masked tail) ----------------
__global__ void softmax_kernel()
{
    int s = blockIdx.x, h = blockIdx.y, tid = threadIdx.x;   // 128 threads
    float* row = g_scores + (size_t)h * S * S + (size_t)s * S;
    int nk = s + 1;
    __shared__ float red[128];
    float m = -1e30f;
    for (int i = tid; i < nk; i += 128) m = fmaxf(m, row[i]);
    red[tid] = m; __syncthreads();
    for (int st = 64; st > 0; st >>= 1) {
        if (tid < st) red[tid] = fmaxf(red[tid], red[tid + st]);
        __syncthreads();
    }
    m = red[0]; __syncthreads();
    float sum = 0.f;
    for (int i = tid; i < nk; i += 128) {
        float e = expf(row[i] - m);
        row[i] = e; sum += e;
    }
    red[tid] = sum; __syncthreads();
    for (int st = 64; st > 0; st >>= 1) {
        if (tid < st) red[tid] += red[tid + st];
        __syncthreads();
    }
    float inv = 1.f / red[0];
    for (int i = tid; i < nk; i += 128) row[i] *= inv;
    for (int i = nk + tid; i < S; i += 128) row[i] = 0.f;
}

// ---------------- attn = P @ V (NN gemm), writes [s][h*HD+d] -----------------
// grid (1, 8, 32)
__global__ __launch_bounds__(256) void pv_kernel()
{
    int h = blockIdx.z, mBase = blockIdx.y * 64;
    int kvh = h / GRP;
    float acc[4][8] = {};
    sgemm_core<false>(g_scores + (size_t)h   * S * S, S, nullptr, mBase,
                      g_vt     + (size_t)kvh * S * HD, HD, 0, S, acc);
    int ty = threadIdx.x >> 4, tx = threadIdx.x & 15;
    #pragma unroll
    for (int i = 0; i < 4; i++)
        #pragma unroll
        for (int j = 0; j < 8; j++)
            g_attn[(size_t)(mBase + ty*4 + i) * NQK + h * HD + tx*8 + j] = acc[i][j];
}

// ---------------- h = x + attn @ wo^T ----------------------------------------
// grid (16, 8)
__global__ __launch_bounds__(256) void wo_kernel(const float* __restrict__ wo_w,
                                                 const float* __restrict__ x,
                                                 float* __restrict__ out)
{
    int nBase = blockIdx.x * 128, mBase = blockIdx.y * 64;
    float acc[4][8] = {};
    sgemm_core<true>(g_attn, NQK, nullptr, mBase, wo_w, NQK, nBase, NQK, acc);
    int ty = threadIdx.x >> 4, tx = threadIdx.x & 15;
    #pragma unroll
    for (int i = 0; i < 4; i++) {
        size_t m = mBase + ty * 4 + i;
        #pragma unroll
        for (int j = 0; j < 8; j++) {
            size_t idx = m * DIM + nBase + tx * 8 + j;
            out[idx] = acc[i][j] + x[idx];
        }
    }
}

// ---------------- router: softmax + top-8 + scatter into expert lists --------
__global__ void router_kernel(const float* __restrict__ rw)
{
    int t = blockIdx.x, tid = threadIdx.x;   // 128 threads
    __shared__ float hrow[DIM];
    __shared__ float logits[NE];
    for (int i = tid; i < DIM; i += 128) hrow[i] = g_hn[(size_t)t * DIM + i];
    __syncthreads();
    if (tid < NE) {
        const float* r = rw + (size_t)tid * DIM;
        float acc = 0.f;
        for (int i = 0; i < DIM; i++) acc += hrow[i] * r[i];
        logits[tid] = acc;
    }
    __syncthreads();
    if (tid == 0) {
        float m = -1e30f;
        for (int e = 0; e < NE; e++) m = fmaxf(m, logits[e]);
        float pr[NE]; float sum = 0.f;
        for (int e = 0; e < NE; e++) { pr[e] = expf(logits[e] - m); sum += pr[e]; }
        float invs = 1.f / sum;
        for (int e = 0; e < NE; e++) pr[e] *= invs;
        int   ti[TOPK]; float tw[TOPK]; float wsum = 0.f;
        for (int kk = 0; kk < TOPK; kk++) {
            int best = 0; float bv = -1.f;
            for (int e = 0; e < NE; e++) if (pr[e] > bv) { bv = pr[e]; best = e; }
            ti[kk] = best; tw[kk] = bv; pr[best] = -2.f; wsum += bv;
        }
        float inv = 1.f / (wsum + 1e-20f);
        for (int kk = 0; kk < TOPK; kk++) {
            int e = ti[kk];
            int pos = atomicAdd(&g_ecnt[e], 1);
            g_etok[e * S + pos] = t;
            g_ew  [e * S + pos] = tw[kk] * inv;
        }
    }
}

// ---------------- MoE gate/up gathered GEMM (raw, no activation yet) ---------
// grid (12, 8, 64): x<6 -> gate tiles, x>=6 -> up tiles
__global__ __launch_bounds__(256) void moe_mid_kernel(
    const float* __restrict__ gate_w, const float* __restrict__ up_w)
{
    int e = blockIdx.z;
    int Me = g_ecnt[e];
    int rowBase = blockIdx.y * 64;
    if (rowBase >= Me) return;
    __shared__ int tok[64];
    if (threadIdx.x < 64)
        tok[threadIdx.x] = g_etok[e * S + min(rowBase + (int)threadIdx.x, Me - 1)];
    __syncthreads();
    int xt = blockIdx.x;
    const float* B; float* C; int nBase;
    if (xt < 6) { B = gate_w + (size_t)e * FF * DIM; nBase = xt * 128;       C = g_midg; }
    else        { B = up_w   + (size_t)e * FF * DIM; nBase = (xt - 6) * 128; C = g_midu; }
    float acc[4][8] = {};
    sgemm_core<true>(g_hn, DIM, tok, 0, B, DIM, nBase, DIM, acc);
    int ty = threadIdx.x >> 4, tx = threadIdx.x & 15;
    #pragma unroll
    for (int i = 0; i < 4; i++) {
        int slot = rowBase + ty * 4 + i;
        if (slot >= Me) continue;
        #pragma unroll
        for (int j = 0; j < 8; j++)
            C[(size_t)(e * S + slot) * FF + nBase + tx * 8 + j] = acc[i][j];
    }
}

// ---------------- elementwise: midg = silu(midg) * midu ----------------------
__global__ void silu_kernel()
{
    int slot = blockIdx.x, e = blockIdx.y;
    if (slot >= g_ecnt[e]) return;
    size_t base = (size_t)(e * S + slot) * FF;
    for (int i = threadIdx.x; i < FF; i += 256) {
        float g = g_midg[base + i], u = g_midu[base + i];
        g_midg[base + i] = g / (1.f + expf(-g)) * u;
    }
}

// ---------------- MoE down GEMM + weighted atomic scatter --------------------
// grid (16, 8, 64)
__global__ __launch_bounds__(256) void moe_down_kernel(
    const float* __restrict__ down_w, float* __restrict__ out)
{
    int e = blockIdx.z;
    int Me = g_ecnt[e];
    int rowBase = blockIdx.y * 64;
    if (rowBase >= Me) return;
    __shared__ int tok[64]; __shared__ float wts[64];
    if (threadIdx.x < 64) {
        int sl = min(rowBase + (int)threadIdx.x, Me - 1);
        tok[threadIdx.x] = g_etok[e * S + sl];
        wts[threadIdx.x] = g_ew  [e * S + sl];
    }
    __syncthreads();
    int nBase = blockIdx.x * 128;
    float acc[4][8] = {};
    sgemm_core<true>(g_midg + (size_t)e * S * FF, FF, nullptr, rowBase,
                     down_w + (size_t)e * DIM * FF, FF, nBase, FF, acc);
    int ty = threadIdx.x >> 4, tx = threadIdx.x & 15;
    #pragma unroll
    for (int i = 0; i < 4; i++) {
        int slot = rowBase + ty * 4 + i;
        if (slot >= Me) continue;
        int t  = tok[ty * 4 + i];
        float w = wts[ty * 4 + i];
        #pragma unroll
        for (int j = 0; j < 8; j++)
            atomicAdd(&out[(size_t)t * DIM + nBase + tx * 8 + j], acc[i][j] * w);
    }
}

// ---------------- launch ------------------------------------------------------
extern "C" void kernel_launch(void* const* d_in, const int* in_sizes, int n_in,
                              void* d_out, int out_size)
{
    const float* x    = (const float*)d_in[0];
    const float* cosp = (const float*)d_in[1];
    const float* sinp = (const float*)d_in[2];
    const float* n1w  = (const float*)d_in[3];
    const float* wq   = (const float*)d_in[4];
    const float* wk   = (const float*)d_in[5];
    const float* wv   = (const float*)d_in[6];
    const float* wo_w = (const float*)d_in[7];
    const float* qnw  = (const float*)d_in[8];
    const float* knw  = (const float*)d_in[9];
    const float* n2w  = (const float*)d_in[10];
    const float* rw   = (const float*)d_in[11];
    const float* gw   = (const float*)d_in[12];
    const float* uw   = (const float*)d_in[13];
    const float* dw   = (const float*)d_in[14];
    float* out = (float*)d_out;

    float *xn, *hn;
    cudaGetSymbolAddress((void**)&xn, g_xn);
    cudaGetSymbolAddress((void**)&hn, g_hn);

    zero_counts_kernel<<<1, 64>>>();
    rmsnorm_kernel<<<S, 256>>>(x, n1w, xn);
    qkv_kernel<<<dim3(H + 2*HK, S/64), 256>>>(xn, wq, wk, wv);
    qknorm_rope_kernel<<<dim3(S, H + HK), HD>>>(qnw, knw, cosp, sinp);
    scores_kernel<<<dim3(S/128, S/64, H), 256>>>();
    softmax_kernel<<<dim3(S, H), 128>>>();
    pv_kernel<<<dim3(1, S/64, H), 256>>>();
    wo_kernel<<<dim3(DIM/128, S/64), 256>>>(wo_w, x, out);
    rmsnorm_kernel<<<S, 256>>>(out, n2w, hn);
    router_kernel<<<S, 128>>>(rw);
    moe_mid_kernel<<<dim3(12, S/64, NE), 256>>>(gw, uw);
    silu_kernel<<<dim3(S, NE), 256>>>();
    moe_down_kernel<<<dim3(DIM/128, S/64, NE), 256>>>(dw, out);
}

// round 6
// speedup vs baseline: 2.0876x; 1.5384x over previous
#include <cuda_runtime.h>
#include <cuda_bf16.h>
#include <math.h>
#include <stdint.h>

#define S    512
#define DIM  2048
#define H    32
#define HK   4
#define HD   128
#define NQK  (H*HD)    // 4096
#define NKV  (HK*HD)   // 512
#define NE   64
#define TOPK 8
#define FF   768
#define EPS  1e-6f
#define GRP  (H/HK)    // 8

// GEMM tile config: BM=64, BN=128, BK=32, 256 threads (8 warps, warp tile 32x32)
#define AW 20   // smem words per row (16 data + 4 pad) -> conflict-free frag LDS

// ---------------- scratch (static device globals; no allocation) -------------
__device__ float g_xn[S*DIM];
__device__ float g_qt[(size_t)H*S*HD];      // [h][s][d]
__device__ float g_kt[(size_t)HK*S*HD];     // [h][s][d]
__device__ float g_vtT[(size_t)HK*HD*S];    // [h][d][s]  (transposed for PV)
__device__ float g_scores[(size_t)H*S*S];
__device__ float g_attn[S*NQK];             // [s][h*HD+d]
__device__ float g_hn[S*DIM];
__device__ float g_midg[(size_t)NE*S*FF];
__device__ float g_midu[(size_t)NE*S*FF];
__device__ int   g_ecnt[NE];
__device__ int   g_etok[NE*S];
__device__ float g_ew  [NE*S];

// ---------------- helpers ----------------------------------------------------
struct SmemT {
    uint32_t Ahi[64*AW];
    uint32_t Alo[64*AW];
    uint32_t Bhi[128*AW];
    uint32_t Blo[128*AW];
};

__device__ __forceinline__ void mma16816(float* c, const uint32_t* a, const uint32_t* b) {
    asm volatile(
        "mma.sync.aligned.m16n8k16.row.col.f32.bf16.bf16.f32 "
        "{%0,%1,%2,%3}, {%4,%5,%6,%7}, {%8,%9}, {%0,%1,%2,%3};"
        : "+f"(c[0]), "+f"(c[1]), "+f"(c[2]), "+f"(c[3])
        : "r"(a[0]), "r"(a[1]), "r"(a[2]), "r"(a[3]), "r"(b[0]), "r"(b[1]));
}

__device__ __forceinline__ void pack_hl(float a, float b, uint32_t& hi, uint32_t& lo) {
    __nv_bfloat162 h = __floats2bfloat162_rn(a, b);
    float ah = __bfloat162float(h.x), bh = __bfloat162float(h.y);
    __nv_bfloat162 l = __floats2bfloat162_rn(a - ah, b - bh);
    hi = *reinterpret_cast<uint32_t*>(&h);
    lo = *reinterpret_cast<uint32_t*>(&l);
}

// =============================================================================
// Core: C[64,128] = A[64,K] @ B[128 rows,K]^T, bf16 hi/lo split, fp32 accum in
// registers. rowTok (smem, 64 ints) gathers A rows if non-null. K % 32 == 0.
// acc layout: acc[mt*4+nt][4], mt in 0..1, nt in 0..3 (warp tile 32x32).
// =============================================================================
__device__ __forceinline__ void mma_gemm(
    SmemT& sm,
    const float* __restrict__ A, int lda, const int* rowTok, int mBase,
    const float* __restrict__ B, int ldb, int nBase, int K,
    float (&acc)[8][4])
{
    const int tid  = threadIdx.x;
    const int lane = tid & 31, wid = tid >> 5;
    const int wm = wid >> 2, wn = wid & 3;

    // global load mapping
    const int rA = tid >> 2, qA = tid & 3;          // A: 64 rows x 8 floats
    const int rB = tid >> 1, hB = tid & 1;          // B: 128 rows x 16 floats
    const int rowA = rowTok ? rowTok[rA] : (mBase + rA);
    const float* Ap = A + (size_t)rowA * lda + qA * 8;
    const float* Bp = B + (size_t)(nBase + rB) * ldb + hB * 16;

    float4 va[2], vb[4];
    va[0] = *(const float4*)(Ap);
    va[1] = *(const float4*)(Ap + 4);
    #pragma unroll
    for (int j = 0; j < 4; j++) vb[j] = *(const float4*)(Bp + j * 4);

    const int nch = K >> 5;
    const int awBase = rA * AW + qA * 4;
    const int bwBase = rB * AW + hB * 8;

    for (int t = 0; t < nch; t++) {
        // convert + store current chunk into smem hi/lo planes
        #pragma unroll
        for (int j = 0; j < 2; j++) {
            uint32_t h0, l0, h1, l1;
            pack_hl(va[j].x, va[j].y, h0, l0);
            pack_hl(va[j].z, va[j].w, h1, l1);
            *(uint2*)&sm.Ahi[awBase + j*2] = make_uint2(h0, h1);
            *(uint2*)&sm.Alo[awBase + j*2] = make_uint2(l0, l1);
        }
        #pragma unroll
        for (int j = 0; j < 4; j++) {
            uint32_t h0, l0, h1, l1;
            pack_hl(vb[j].x, vb[j].y, h0, l0);
            pack_hl(vb[j].z, vb[j].w, h1, l1);
            *(uint2*)&sm.Bhi[bwBase + j*2] = make_uint2(h0, h1);
            *(uint2*)&sm.Blo[bwBase + j*2] = make_uint2(l0, l1);
        }
        __syncthreads();

        if (t + 1 < nch) {   // prefetch next chunk
            va[0] = *(const float4*)(Ap + (t+1)*32);
            va[1] = *(const float4*)(Ap + (t+1)*32 + 4);
            #pragma unroll
            for (int j = 0; j < 4; j++)
                vb[j] = *(const float4*)(Bp + (t+1)*32 + j*4);
        }

        // two k16 steps
        #pragma unroll
        for (int ks = 0; ks < 2; ks++) {
            const int kw = ks * 8;
            uint32_t ah[2][4], al[2][4], bh[4][2], bl[4][2];
            #pragma unroll
            for (int mt = 0; mt < 2; mt++) {
                int r0 = (wm*32 + mt*16 + (lane>>2)) * AW + kw + (lane&3);
                int r1 = r0 + 8*AW;
                ah[mt][0] = sm.Ahi[r0];     ah[mt][1] = sm.Ahi[r1];
                ah[mt][2] = sm.Ahi[r0+4];   ah[mt][3] = sm.Ahi[r1+4];
                al[mt][0] = sm.Alo[r0];     al[mt][1] = sm.Alo[r1];
                al[mt][2] = sm.Alo[r0+4];   al[mt][3] = sm.Alo[r1+4];
            }
            #pragma unroll
            for (int nt = 0; nt < 4; nt++) {
                int n0 = (wn*32 + nt*8 + (lane>>2)) * AW + kw + (lane&3);
                bh[nt][0] = sm.Bhi[n0];  bh[nt][1] = sm.Bhi[n0+4];
                bl[nt][0] = sm.Blo[n0];  bl[nt][1] = sm.Blo[n0+4];
            }
            #pragma unroll
            for (int mt = 0; mt < 2; mt++)
                #pragma unroll
                for (int nt = 0; nt < 4; nt++) {
                    mma16816(acc[mt*4+nt], ah[mt], bh[nt]);
                    mma16816(acc[mt*4+nt], ah[mt], bl[nt]);
                    mma16816(acc[mt*4+nt], al[mt], bh[nt]);
                }
        }
        __syncthreads();
    }
}

// ---------------- small utility kernels --------------------------------------
__global__ void zero_counts_kernel() {
    if (threadIdx.x < NE) g_ecnt[threadIdx.x] = 0;
}

__global__ void rmsnorm_kernel(const float* __restrict__ x,
                               const float* __restrict__ w,
                               float* __restrict__ out) {
    int row = blockIdx.x;
    const float* xr = x + (size_t)row * DIM;
    float ss = 0.f;
    for (int i = threadIdx.x; i < DIM; i += 256) { float v = xr[i]; ss += v * v; }
    __shared__ float red[256];
    red[threadIdx.x] = ss; __syncthreads();
    for (int st = 128; st > 0; st >>= 1) {
        if (threadIdx.x < st) red[threadIdx.x] += red[threadIdx.x + st];
        __syncthreads();
    }
    float rstd = rsqrtf(red[0] / (float)DIM + EPS);
    for (int i = threadIdx.x; i < DIM; i += 256)
        out[(size_t)row * DIM + i] = xr[i] * rstd * w[i];
}

__global__ void qknorm_rope_kernel(const float* __restrict__ qnw,
                                   const float* __restrict__ knw,
                                   const float* __restrict__ cosp,
                                   const float* __restrict__ sinp)
{
    int s = blockIdx.x, h2 = blockIdx.y, d = threadIdx.x;   // 128 threads
    float* ptr; const float* w;
    if (h2 < H) { ptr = g_qt + (size_t)h2       * S * HD + (size_t)s * HD; w = qnw; }
    else        { ptr = g_kt + (size_t)(h2 - H) * S * HD + (size_t)s * HD; w = knw; }
    __shared__ float row[HD];
    __shared__ float red[HD];
    float v = ptr[d];
    red[d] = v * v; __syncthreads();
    for (int st = 64; st > 0; st >>= 1) {
        if (d < st) red[d] += red[d + st];
        __syncthreads();
    }
    float rstd = rsqrtf(red[0] / (float)HD + EPS);
    row[d] = v * rstd * w[d];
    __syncthreads();
    float rot = (d < 64) ? -row[d + 64] : row[d - 64];
    ptr[d] = row[d] * cosp[s * HD + d] + rot * sinp[s * HD + d];
}

__global__ void softmax_kernel()
{
    int s = blockIdx.x, h = blockIdx.y, tid = threadIdx.x;   // 128 threads
    float* row = g_scores + (size_t)h * S * S + (size_t)s * S;
    int nk = s + 1;
    __shared__ float red[128];
    float m = -1e30f;
    for (int i = tid; i < nk; i += 128) m = fmaxf(m, row[i]);
    red[tid] = m; __syncthreads();
    for (int st = 64; st > 0; st >>= 1) {
        if (tid < st) red[tid] = fmaxf(red[tid], red[tid + st]);
        __syncthreads();
    }
    m = red[0]; __syncthreads();
    float sum = 0.f;
    for (int i = tid; i < nk; i += 128) {
        float e = expf(row[i] - m);
        row[i] = e; sum += e;
    }
    red[tid] = sum; __syncthreads();
    for (int st = 64; st > 0; st >>= 1) {
        if (tid < st) red[tid] += red[tid + st];
        __syncthreads();
    }
    float inv = 1.f / red[0];
    for (int i = tid; i < nk; i += 128) row[i] *= inv;
    for (int i = nk + tid; i < S; i += 128) row[i] = 0.f;
}

__global__ void router_kernel(const float* __restrict__ rw)
{
    int t = blockIdx.x, tid = threadIdx.x;   // 128 threads
    __shared__ float hrow[DIM];
    __shared__ float logits[NE];
    for (int i = tid; i < DIM; i += 128) hrow[i] = g_hn[(size_t)t * DIM + i];
    __syncthreads();
    if (tid < NE) {
        const float* r = rw + (size_t)tid * DIM;
        float acc = 0.f;
        for (int i = 0; i < DIM; i++) acc += hrow[i] * r[i];
        logits[tid] = acc;
    }
    __syncthreads();
    if (tid == 0) {
        float m = -1e30f;
        for (int e = 0; e < NE; e++) m = fmaxf(m, logits[e]);
        float pr[NE]; float sum = 0.f;
        for (int e = 0; e < NE; e++) { pr[e] = expf(logits[e] - m); sum += pr[e]; }
        float invs = 1.f / sum;
        for (int e = 0; e < NE; e++) pr[e] *= invs;
        int   ti[TOPK]; float tw[TOPK]; float wsum = 0.f;
        for (int kk = 0; kk < TOPK; kk++) {
            int best = 0; float bv = -1.f;
            for (int e = 0; e < NE; e++) if (pr[e] > bv) { bv = pr[e]; best = e; }
            ti[kk] = best; tw[kk] = bv; pr[best] = -2.f; wsum += bv;
        }
        float inv = 1.f / (wsum + 1e-20f);
        for (int kk = 0; kk < TOPK; kk++) {
            int e = ti[kk];
            int pos = atomicAdd(&g_ecnt[e], 1);
            g_etok[e * S + pos] = t;
            g_ew  [e * S + pos] = tw[kk] * inv;
        }
    }
}

__global__ void silu_kernel()
{
    int slot = blockIdx.x, e = blockIdx.y;
    if (slot >= g_ecnt[e]) return;
    size_t base = (size_t)(e * S + slot) * FF;
    for (int i = threadIdx.x; i < FF; i += 256) {
        float g = g_midg[base + i], u = g_midu[base + i];
        g_midg[base + i] = g / (1.f + expf(-g)) * u;
    }
}

// ================== HMMA GEMM kernels =========================================

// QKV: grid (40, 8). x<32: q head; [32,36): k head; [36,40): v head (-> V^T).
__global__ __launch_bounds__(256) void qkv_kernel(
    const float* __restrict__ xn, const float* __restrict__ wq,
    const float* __restrict__ wk, const float* __restrict__ wv)
{
    __shared__ SmemT sm;
    int nt = blockIdx.x, mBase = blockIdx.y * 64;
    const float* B; int head, fam;
    if (nt < H)           { B = wq; head = nt;          fam = 0; }
    else if (nt < H + HK) { B = wk; head = nt - H;      fam = 1; }
    else                  { B = wv; head = nt - H - HK; fam = 2; }
    float acc[8][4] = {};
    mma_gemm(sm, xn, DIM, nullptr, mBase, B, DIM, head * HD, DIM, acc);
    int lane = threadIdx.x & 31, wid = threadIdx.x >> 5;
    int wm = wid >> 2, wn = wid & 3;
    #pragma unroll
    for (int mt = 0; mt < 2; mt++)
        #pragma unroll
        for (int ntl = 0; ntl < 4; ntl++) {
            int r0  = mBase + wm*32 + mt*16 + (lane>>2);
            int col = wn*32 + ntl*8 + (lane&3)*2;
            float* a = acc[mt*4+ntl];
            if (fam == 0) {
                float* o = g_qt + (size_t)head*S*HD;
                *(float2*)&o[(size_t)r0*HD + col]     = make_float2(a[0], a[1]);
                *(float2*)&o[(size_t)(r0+8)*HD + col] = make_float2(a[2], a[3]);
            } else if (fam == 1) {
                float* o = g_kt + (size_t)head*S*HD;
                *(float2*)&o[(size_t)r0*HD + col]     = make_float2(a[0], a[1]);
                *(float2*)&o[(size_t)(r0+8)*HD + col] = make_float2(a[2], a[3]);
            } else {
                float* o = g_vtT + (size_t)head*HD*S;
                o[(size_t)col*S     + r0]     = a[0];
                o[(size_t)(col+1)*S + r0]     = a[1];
                o[(size_t)col*S     + r0 + 8] = a[2];
                o[(size_t)(col+1)*S + r0 + 8] = a[3];
            }
        }
}

// scores: grid (4, 8, 32). Skip fully-masked tiles.
__global__ __launch_bounds__(256) void scores_kernel()
{
    int h = blockIdx.z, mBase = blockIdx.y * 64, nBase = blockIdx.x * 128;
    if (nBase > mBase + 63) return;
    __shared__ SmemT sm;
    int kvh = h / GRP;
    float acc[8][4] = {};
    mma_gemm(sm, g_qt + (size_t)h * S * HD, HD, nullptr, mBase,
             g_kt + (size_t)kvh * S * HD, HD, nBase, HD, acc);
    const float alpha = 0.08838834764831845f;   // 1/sqrt(128)
    float* C = g_scores + (size_t)h * S * S;
    int lane = threadIdx.x & 31, wid = threadIdx.x >> 5;
    int wm = wid >> 2, wn = wid & 3;
    #pragma unroll
    for (int mt = 0; mt < 2; mt++)
        #pragma unroll
        for (int ntl = 0; ntl < 4; ntl++) {
            int r0  = mBase + wm*32 + mt*16 + (lane>>2);
            int col = nBase + wn*32 + ntl*8 + (lane&3)*2;
            float* a = acc[mt*4+ntl];
            *(float2*)&C[(size_t)r0*S + col]     = make_float2(a[0]*alpha, a[1]*alpha);
            *(float2*)&C[(size_t)(r0+8)*S + col] = make_float2(a[2]*alpha, a[3]*alpha);
        }
}

// pv: grid (1, 8, 32). A = softmaxed scores, B = V^T.
__global__ __launch_bounds__(256) void pv_kernel()
{
    __shared__ SmemT sm;
    int h = blockIdx.z, mBase = blockIdx.y * 64;
    int kvh = h / GRP;
    float acc[8][4] = {};
    mma_gemm(sm, g_scores + (size_t)h * S * S, S, nullptr, mBase,
             g_vtT + (size_t)kvh * HD * S, S, 0, S, acc);
    int lane = threadIdx.x & 31, wid = threadIdx.x >> 5;
    int wm = wid >> 2, wn = wid & 3;
    #pragma unroll
    for (int mt = 0; mt < 2; mt++)
        #pragma unroll
        for (int ntl = 0; ntl < 4; ntl++) {
            int r0  = mBase + wm*32 + mt*16 + (lane>>2);
            int col = h*HD + wn*32 + ntl*8 + (lane&3)*2;
            float* a = acc[mt*4+ntl];
            *(float2*)&g_attn[(size_t)r0*NQK + col]     = make_float2(a[0], a[1]);
            *(float2*)&g_attn[(size_t)(r0+8)*NQK + col] = make_float2(a[2], a[3]);
        }
}

// wo: grid (16, 8). out = attn @ wo^T + x  -> d_out
__global__ __launch_bounds__(256) void wo_kernel(
    const float* __restrict__ wo_w, const float* __restrict__ x,
    float* __restrict__ out)
{
    __shared__ SmemT sm;
    int nBase = blockIdx.x * 128, mBase = blockIdx.y * 64;
    float acc[8][4] = {};
    mma_gemm(sm, g_attn, NQK, nullptr, mBase, wo_w, NQK, nBase, NQK, acc);
    int lane = threadIdx.x & 31, wid = threadIdx.x >> 5;
    int wm = wid >> 2, wn = wid & 3;
    #pragma unroll
    for (int mt = 0; mt < 2; mt++)
        #pragma unroll
        for (int ntl = 0; ntl < 4; ntl++) {
            int r0  = mBase + wm*32 + mt*16 + (lane>>2);
            int col = nBase + wn*32 + ntl*8 + (lane&3)*2;
            float* a = acc[mt*4+ntl];
            size_t i0 = (size_t)r0*DIM + col, i1 = (size_t)(r0+8)*DIM + col;
            float2 x0 = *(const float2*)&x[i0], x1 = *(const float2*)&x[i1];
            *(float2*)&out[i0] = make_float2(a[0] + x0.x, a[1] + x0.y);
            *(float2*)&out[i1] = make_float2(a[2] + x1.x, a[3] + x1.y);
        }
}

// moe mid: grid (12, 8, 64). x<6 gate, else up. Gathered A rows.
__global__ __launch_bounds__(256) void moe_mid_kernel(
    const float* __restrict__ gate_w, const float* __restrict__ up_w)
{
    int e = blockIdx.z;
    int Me = g_ecnt[e];
    int rowBase = blockIdx.y * 64;
    if (rowBase >= Me) return;
    __shared__ SmemT sm;
    __shared__ int tok[64];
    if (threadIdx.x < 64)
        tok[threadIdx.x] = g_etok[e * S + min(rowBase + (int)threadIdx.x, Me - 1)];
    __syncthreads();
    int xt = blockIdx.x;
    const float* B; float* C; int nBase;
    if (xt < 6) { B = gate_w + (size_t)e * FF * DIM; nBase = xt * 128;       C = g_midg; }
    else        { B = up_w   + (size_t)e * FF * DIM; nBase = (xt - 6) * 128; C = g_midu; }
    float acc[8][4] = {};
    mma_gemm(sm, g_hn, DIM, tok, 0, B, DIM, nBase, DIM, acc);
    int lane = threadIdx.x & 31, wid = threadIdx.x >> 5;
    int wm = wid >> 2, wn = wid & 3;
    #pragma unroll
    for (int mt = 0; mt < 2; mt++)
        #pragma unroll
        for (int ntl = 0; ntl < 4; ntl++) {
            int lr  = wm*32 + mt*16 + (lane>>2);
            int col = nBase + wn*32 + ntl*8 + (lane&3)*2;
            float* a = acc[mt*4+ntl];
            int s0 = rowBase + lr, s1 = s0 + 8;
            if (s0 < Me)
                *(float2*)&C[(size_t)(e*S + s0)*FF + col] = make_float2(a[0], a[1]);
            if (s1 < Me)
                *(float2*)&C[(size_t)(e*S + s1)*FF + col] = make_float2(a[2], a[3]);
        }
}

// moe down: grid (16, 8, 64). Weighted atomic scatter onto out.
__global__ __launch_bounds__(256) void moe_down_kernel(
    const float* __restrict__ down_w, float* __restrict__ out)
{
    int e = blockIdx.z;
    int Me = g_ecnt[e];
    int rowBase = blockIdx.y * 64;
    if (rowBase >= Me) return;
    __shared__ SmemT sm;
    __shared__ int tok[64];
    __shared__ float wts[64];
    if (threadIdx.x < 64) {
        int sl = min(rowBase + (int)threadIdx.x, Me - 1);
        tok[threadIdx.x] = g_etok[e * S + sl];
        wts[threadIdx.x] = g_ew  [e * S + sl];
    }
    __syncthreads();
    int nBase = blockIdx.x * 128;
    float acc[8][4] = {};
    mma_gemm(sm, g_midg + (size_t)e * S * FF, FF, nullptr, rowBase,
             down_w + (size_t)e * DIM * FF, FF, nBase, FF, acc);
    int lane = threadIdx.x & 31, wid = threadIdx.x >> 5;
    int wm = wid >> 2, wn = wid & 3;
    #pragma unroll
    for (int mt = 0; mt < 2; mt++)
        #pragma unroll
        for (int ntl = 0; ntl < 4; ntl++) {
            int lr  = wm*32 + mt*16 + (lane>>2);
            int col = nBase + wn*32 + ntl*8 + (lane&3)*2;
            float* a = acc[mt*4+ntl];
            int s0 = rowBase + lr, s1 = s0 + 8;
            if (s0 < Me) {
                int t = tok[lr]; float w = wts[lr];
                atomicAdd(&out[(size_t)t*DIM + col],     a[0]*w);
                atomicAdd(&out[(size_t)t*DIM + col + 1], a[1]*w);
            }
            if (s1 < Me) {
                int t = tok[lr+8]; float w = wts[lr+8];
                atomicAdd(&out[(size_t)t*DIM + col],     a[2]*w);
                atomicAdd(&out[(size_t)t*DIM + col + 1], a[3]*w);
            }
        }
}

// ---------------- launch ------------------------------------------------------
extern "C" void kernel_launch(void* const* d_in, const int* in_sizes, int n_in,
                              void* d_out, int out_size)
{
    const float* x    = (const float*)d_in[0];
    const float* cosp = (const float*)d_in[1];
    const float* sinp = (const float*)d_in[2];
    const float* n1w  = (const float*)d_in[3];
    const float* wq   = (const float*)d_in[4];
    const float* wk   = (const float*)d_in[5];
    const float* wv   = (const float*)d_in[6];
    const float* wo_w = (const float*)d_in[7];
    const float* qnw  = (const float*)d_in[8];
    const float* knw  = (const float*)d_in[9];
    const float* n2w  = (const float*)d_in[10];
    const float* rw   = (const float*)d_in[11];
    const float* gw   = (const float*)d_in[12];
    const float* uw   = (const float*)d_in[13];
    const float* dw   = (const float*)d_in[14];
    float* out = (float*)d_out;

    float *xn, *hn;
    cudaGetSymbolAddress((void**)&xn, g_xn);
    cudaGetSymbolAddress((void**)&hn, g_hn);

    zero_counts_kernel<<<1, 64>>>();
    rmsnorm_kernel<<<S, 256>>>(x, n1w, xn);
    qkv_kernel<<<dim3(H + 2*HK, S/64), 256>>>(xn, wq, wk, wv);
    qknorm_rope_kernel<<<dim3(S, H + HK), HD>>>(qnw, knw, cosp, sinp);
    scores_kernel<<<dim3(S/128, S/64, H), 256>>>();
    softmax_kernel<<<dim3(S, H), 128>>>();
    pv_kernel<<<dim3(1, S/64, H), 256>>>();
    wo_kernel<<<dim3(DIM/128, S/64), 256>>>(wo_w, x, out);
    rmsnorm_kernel<<<S, 256>>>(out, n2w, hn);
    router_kernel<<<S, 128>>>(rw);
    moe_mid_kernel<<<dim3(12, S/64, NE), 256>>>(gw, uw);
    silu_kernel<<<dim3(S, NE), 256>>>();
    moe_down_kernel<<<dim3(DIM/128, S/64, NE), 256>>>(dw, out);
}